// round 6
// baseline (speedup 1.0000x reference)
#include <cuda_runtime.h>
#include <cuda_bf16.h>
#include <math.h>

// Problem constants
#define Dm   1024
#define Hh   4096
#define Ee   8
#define Kk   2
#define Tt   8192          // B*S = 4*2048
#define CAPc 2560          // ceil(1.25 * T*K / E)

// GEMM tiling
#define BM 128
#define BN 128
#define BKK 8

// ---------------- device scratch (static globals; no cudaMalloc allowed) ----
__device__ int   g_eidx[Tt * Kk];
__device__ float g_w[Tt * Kk];
__device__ int   g_dest[Tt * Kk];
__device__ int   g_slot_token[Ee * CAPc];
__device__ int   g_cnt[Ee];
__device__ float g_h[(size_t)Ee * CAPc * Hh];   // expert hidden activations (~335 MB)
__device__ float g_o[(size_t)Ee * CAPc * Dm];   // expert outputs (~84 MB)

// ---------------- f32x2 packed FMA helpers (FFMA2: 2x fp32 rate on sm_103a) --
__device__ __forceinline__ unsigned long long pk2(float lo, float hi) {
    unsigned long long r;
    asm("mov.b64 %0, {%1, %2};" : "=l"(r) : "f"(lo), "f"(hi));
    return r;
}
__device__ __forceinline__ void upk2(unsigned long long v, float& lo, float& hi) {
    asm("mov.b64 {%0, %1}, %2;" : "=f"(lo), "=f"(hi) : "l"(v));
}
#define FMA2(acc, a, b) asm("fma.rn.f32x2 %0, %1, %2, %0;" : "+l"(acc) : "l"(a), "l"(b))

__device__ __forceinline__ float gelu_tanh(float v) {
    // jax.nn.gelu default: approximate=True (tanh form)
    float u = 0.7978845608028654f * (v + 0.044715f * v * v * v);
    return 0.5f * v * (1.0f + tanhf(u));
}

// ---------------- 1) Router: logits, top-2, renormalized softmax weights ----
__global__ void router_kernel(const float* __restrict__ x,
                              const float* __restrict__ Wr) {
    __shared__ float sWrT[Ee * Dm];   // transposed [e][d], 32 KB
    for (int i = threadIdx.x; i < Dm * Ee; i += 256) {
        int d = i / Ee, e = i % Ee;
        sWrT[e * Dm + d] = Wr[i];
    }
    __syncthreads();

    int warp = threadIdx.x >> 5, lane = threadIdx.x & 31;
    int t = blockIdx.x * 8 + warp;
    const float* xr = x + (size_t)t * Dm;

    float acc[Ee];
#pragma unroll
    for (int e = 0; e < Ee; e++) acc[e] = 0.f;

    for (int d = lane * 4; d < Dm; d += 128) {
        float4 xv = *(const float4*)(xr + d);
#pragma unroll
        for (int e = 0; e < Ee; e++) {
            float4 wv = *(const float4*)(&sWrT[e * Dm + d]);
            acc[e] += xv.x * wv.x + xv.y * wv.y + xv.z * wv.z + xv.w * wv.w;
        }
    }
#pragma unroll
    for (int e = 0; e < Ee; e++) {
#pragma unroll
        for (int off = 16; off > 0; off >>= 1)
            acc[e] += __shfl_xor_sync(0xffffffffu, acc[e], off);
    }
    if (lane == 0) {
        int e0 = 0;
        float l0 = acc[0];
#pragma unroll
        for (int e = 1; e < Ee; e++) if (acc[e] > l0) { l0 = acc[e]; e0 = e; }
        int e1 = -1;
        float l1 = -3.4e38f;
#pragma unroll
        for (int e = 0; e < Ee; e++) {
            if (e == e0) continue;
            if (acc[e] > l1) { l1 = acc[e]; e1 = e; }
        }
        float r = __expf(l1 - l0);           // <= 1
        float w0 = 1.0f / (1.0f + r);
        g_eidx[t * 2 + 0] = e0;
        g_eidx[t * 2 + 1] = e1;
        g_w[t * 2 + 0] = w0;
        g_w[t * 2 + 1] = 1.0f - w0;
    }
}

// ---------------- 2) Dispatch: pair-order cumsum per expert, capacity -------
__global__ void dispatch_kernel() {
    __shared__ int sc[256 * Ee];
    int tid = threadIdx.x;
    int base = tid * 64;               // 16384 pairs / 256 threads
    int lc[Ee];
#pragma unroll
    for (int e = 0; e < Ee; e++) lc[e] = 0;
    for (int p = base; p < base + 64; p++) lc[g_eidx[p]]++;
#pragma unroll
    for (int e = 0; e < Ee; e++) sc[tid * Ee + e] = lc[e];
    __syncthreads();
    if (tid < Ee) {
        int run = 0;
        for (int i = 0; i < 256; i++) {
            int v = sc[i * Ee + tid];
            sc[i * Ee + tid] = run;
            run += v;
        }
        g_cnt[tid] = run < CAPc ? run : CAPc;
    }
    __syncthreads();
    int off[Ee];
#pragma unroll
    for (int e = 0; e < Ee; e++) off[e] = sc[tid * Ee + e];
    for (int p = base; p < base + 64; p++) {
        int e = g_eidx[p];
        int pos = off[e]++;
        if (pos < CAPc) {
            int d = e * CAPc + pos;
            g_slot_token[d] = p >> 1;      // token id
            g_dest[p] = d;
        } else {
            g_dest[p] = -1;
        }
    }
}

// ---------------- 3) GEMM1: h = gelu(gather(x) @ W1[e] + b1[e]) -------------
__global__ void __launch_bounds__(256, 2)
gemm1_kernel(const float* __restrict__ x,
             const float* __restrict__ W1,
             const float* __restrict__ b1) {
    int e = blockIdx.z;
    int cnt = g_cnt[e];
    int m0 = blockIdx.y * BM;
    if (m0 >= cnt) return;
    int n0 = blockIdx.x * BN;

    __shared__ float As[BKK][BM];
    __shared__ float Bs[BKK][BN];

    int tid = threadIdx.x;
    int tx = tid & 15, ty = tid >> 4;

    // A-load assignment: each thread loads one float4 of one row
    int lrow = tid >> 1;
    int lq = (tid & 1) * 4;
    int gm = m0 + lrow;
    const float* arow = nullptr;
    if (gm < cnt) arow = x + (size_t)g_slot_token[e * CAPc + gm] * Dm;

    // B-load assignment
    int bk = tid >> 5;
    int bn4 = (tid & 31) * 4;
    const float* Wbase = W1 + (size_t)e * Dm * Hh;

    unsigned long long acc[8][4];
#pragma unroll
    for (int i = 0; i < 8; i++)
#pragma unroll
        for (int j = 0; j < 4; j++) acc[i][j] = 0ull;

    for (int k0 = 0; k0 < Dm; k0 += BKK) {
        float4 av = make_float4(0.f, 0.f, 0.f, 0.f);
        if (arow) av = *(const float4*)(arow + k0 + lq);
        As[lq + 0][lrow] = av.x;
        As[lq + 1][lrow] = av.y;
        As[lq + 2][lrow] = av.z;
        As[lq + 3][lrow] = av.w;
        *(float4*)&Bs[bk][bn4] =
            *(const float4*)(Wbase + (size_t)(k0 + bk) * Hh + n0 + bn4);
        __syncthreads();
#pragma unroll
        for (int kk = 0; kk < BKK; kk++) {
            float4 a0 = *(const float4*)&As[kk][ty * 8];
            float4 a1 = *(const float4*)&As[kk][ty * 8 + 4];
            float4 bq0 = *(const float4*)&Bs[kk][tx * 8];
            float4 bq1 = *(const float4*)&Bs[kk][tx * 8 + 4];
            unsigned long long bp[4];
            bp[0] = pk2(bq0.x, bq0.y); bp[1] = pk2(bq0.z, bq0.w);
            bp[2] = pk2(bq1.x, bq1.y); bp[3] = pk2(bq1.z, bq1.w);
            float aa[8] = {a0.x, a0.y, a0.z, a0.w, a1.x, a1.y, a1.z, a1.w};
#pragma unroll
            for (int i = 0; i < 8; i++) {
                unsigned long long ap = pk2(aa[i], aa[i]);
#pragma unroll
                for (int j = 0; j < 4; j++) FMA2(acc[i][j], ap, bp[j]);
            }
        }
        __syncthreads();
    }

    // epilogue: bias + gelu
#pragma unroll
    for (int i = 0; i < 8; i++) {
        int row = m0 + ty * 8 + i;
        float* hr = g_h + ((size_t)(e * CAPc + row)) * Hh;
#pragma unroll
        for (int j = 0; j < 4; j++) {
            float v0, v1;
            upk2(acc[i][j], v0, v1);
            int c = n0 + tx * 8 + j * 2;
            hr[c + 0] = gelu_tanh(v0 + b1[e * Hh + c + 0]);
            hr[c + 1] = gelu_tanh(v1 + b1[e * Hh + c + 1]);
        }
    }
}

// ---------------- 4) GEMM2: out = h @ W2[e] + b2[e] -------------------------
__global__ void __launch_bounds__(256, 2)
gemm2_kernel(const float* __restrict__ W2,
             const float* __restrict__ b2) {
    int e = blockIdx.z;
    int cnt = g_cnt[e];
    int m0 = blockIdx.y * BM;
    if (m0 >= cnt) return;
    int n0 = blockIdx.x * BN;

    __shared__ float As[BKK][BM];
    __shared__ float Bs[BKK][BN];

    int tid = threadIdx.x;
    int tx = tid & 15, ty = tid >> 4;

    int lrow = tid >> 1;
    int lq = (tid & 1) * 4;
    const float* arow = g_h + (size_t)(e * CAPc + m0 + lrow) * Hh;

    int bk = tid >> 5;
    int bn4 = (tid & 31) * 4;
    const float* Wbase = W2 + (size_t)e * Hh * Dm;

    unsigned long long acc[8][4];
#pragma unroll
    for (int i = 0; i < 8; i++)
#pragma unroll
        for (int j = 0; j < 4; j++) acc[i][j] = 0ull;

    for (int k0 = 0; k0 < Hh; k0 += BKK) {
        float4 av = *(const float4*)(arow + k0 + lq);
        As[lq + 0][lrow] = av.x;
        As[lq + 1][lrow] = av.y;
        As[lq + 2][lrow] = av.z;
        As[lq + 3][lrow] = av.w;
        *(float4*)&Bs[bk][bn4] =
            *(const float4*)(Wbase + (size_t)(k0 + bk) * Dm + n0 + bn4);
        __syncthreads();
#pragma unroll
        for (int kk = 0; kk < BKK; kk++) {
            float4 a0 = *(const float4*)&As[kk][ty * 8];
            float4 a1 = *(const float4*)&As[kk][ty * 8 + 4];
            float4 bq0 = *(const float4*)&Bs[kk][tx * 8];
            float4 bq1 = *(const float4*)&Bs[kk][tx * 8 + 4];
            unsigned long long bp[4];
            bp[0] = pk2(bq0.x, bq0.y); bp[1] = pk2(bq0.z, bq0.w);
            bp[2] = pk2(bq1.x, bq1.y); bp[3] = pk2(bq1.z, bq1.w);
            float aa[8] = {a0.x, a0.y, a0.z, a0.w, a1.x, a1.y, a1.z, a1.w};
#pragma unroll
            for (int i = 0; i < 8; i++) {
                unsigned long long ap = pk2(aa[i], aa[i]);
#pragma unroll
                for (int j = 0; j < 4; j++) FMA2(acc[i][j], ap, bp[j]);
            }
        }
        __syncthreads();
    }

#pragma unroll
    for (int i = 0; i < 8; i++) {
        int row = m0 + ty * 8 + i;
        float* orow = g_o + ((size_t)(e * CAPc + row)) * Dm;
#pragma unroll
        for (int j = 0; j < 4; j++) {
            float v0, v1;
            upk2(acc[i][j], v0, v1);
            int c = n0 + tx * 8 + j * 2;
            orow[c + 0] = v0 + b2[e * Dm + c + 0];
            orow[c + 1] = v1 + b2[e * Dm + c + 1];
        }
    }
}

// ---------------- 5) Combine: y[t] = sum_k w * out[dest] --------------------
__global__ void combine_kernel(float* __restrict__ y) {
    int t = blockIdx.x;
    int c4 = threadIdx.x * 4;
    float4 acc = make_float4(0.f, 0.f, 0.f, 0.f);
#pragma unroll
    for (int k = 0; k < Kk; k++) {
        int dst = g_dest[t * 2 + k];
        if (dst >= 0) {
            float w = g_w[t * 2 + k];
            float4 o = *(const float4*)(g_o + (size_t)dst * Dm + c4);
            acc.x += w * o.x;
            acc.y += w * o.y;
            acc.z += w * o.z;
            acc.w += w * o.w;
        }
    }
    *(float4*)(y + (size_t)t * Dm + c4) = acc;
}

// ---------------- launch ----------------------------------------------------
extern "C" void kernel_launch(void* const* d_in, const int* in_sizes, int n_in,
                              void* d_out, int out_size) {
    const float* x  = (const float*)d_in[0];
    const float* Wr = (const float*)d_in[1];
    const float* W1 = (const float*)d_in[2];
    const float* b1 = (const float*)d_in[3];
    const float* W2 = (const float*)d_in[4];
    const float* b2 = (const float*)d_in[5];
    float* y = (float*)d_out;

    router_kernel<<<Tt / 8, 256>>>(x, Wr);
    dispatch_kernel<<<1, 256>>>();
    gemm1_kernel<<<dim3(Hh / BN, CAPc / BM, Ee), 256>>>(x, W1, b1);
    gemm2_kernel<<<dim3(Dm / BN, CAPc / BM, Ee), 256>>>(W2, b2);
    combine_kernel<<<Tt, 256>>>(y);
}

// round 10
// speedup vs baseline: 1.0010x; 1.0010x over previous
#include <cuda_runtime.h>
#include <cuda_bf16.h>
#include <math.h>

// Problem constants
#define Dm   1024
#define Hh   4096
#define Ee   8
#define Kk   2
#define Tt   8192          // B*S = 4*2048
#define CAPc 2560          // ceil(1.25 * T*K / E)

// GEMM tiling
#define BM 128
#define BN 128
#define BKK 8

// ---------------- device scratch (static globals; no cudaMalloc allowed) ----
__device__ int   g_eidx[Tt * Kk];
__device__ float g_w[Tt * Kk];
__device__ int   g_dest[Tt * Kk];
__device__ int   g_slot_token[Ee * CAPc];
__device__ int   g_cnt[Ee];
__device__ float g_h[(size_t)Ee * CAPc * Hh];   // expert hidden activations (~335 MB)
__device__ float g_o[(size_t)Ee * CAPc * Dm];   // expert outputs (~84 MB)

// ---------------- f32x2 packed FMA helpers (FFMA2: 2x fp32 rate on sm_103a) --
__device__ __forceinline__ unsigned long long pk2(float lo, float hi) {
    unsigned long long r;
    asm("mov.b64 %0, {%1, %2};" : "=l"(r) : "f"(lo), "f"(hi));
    return r;
}
__device__ __forceinline__ void upk2(unsigned long long v, float& lo, float& hi) {
    asm("mov.b64 {%0, %1}, %2;" : "=f"(lo), "=f"(hi) : "l"(v));
}
#define FMA2(acc, a, b) asm("fma.rn.f32x2 %0, %1, %2, %0;" : "+l"(acc) : "l"(a), "l"(b))

__device__ __forceinline__ float gelu_tanh(float v) {
    // jax.nn.gelu default: approximate=True (tanh form)
    float u = 0.7978845608028654f * (v + 0.044715f * v * v * v);
    return 0.5f * v * (1.0f + tanhf(u));
}

// ---------------- 1) Router: logits, top-2, renormalized softmax weights ----
__global__ void router_kernel(const float* __restrict__ x,
                              const float* __restrict__ Wr) {
    __shared__ float sWrT[Ee * Dm];   // transposed [e][d], 32 KB
    for (int i = threadIdx.x; i < Dm * Ee; i += 256) {
        int d = i / Ee, e = i % Ee;
        sWrT[e * Dm + d] = Wr[i];
    }
    __syncthreads();

    int warp = threadIdx.x >> 5, lane = threadIdx.x & 31;
    int t = blockIdx.x * 8 + warp;
    const float* xr = x + (size_t)t * Dm;

    float acc[Ee];
#pragma unroll
    for (int e = 0; e < Ee; e++) acc[e] = 0.f;

    for (int d = lane * 4; d < Dm; d += 128) {
        float4 xv = *(const float4*)(xr + d);
#pragma unroll
        for (int e = 0; e < Ee; e++) {
            float4 wv = *(const float4*)(&sWrT[e * Dm + d]);
            acc[e] += xv.x * wv.x + xv.y * wv.y + xv.z * wv.z + xv.w * wv.w;
        }
    }
#pragma unroll
    for (int e = 0; e < Ee; e++) {
#pragma unroll
        for (int off = 16; off > 0; off >>= 1)
            acc[e] += __shfl_xor_sync(0xffffffffu, acc[e], off);
    }
    if (lane == 0) {
        int e0 = 0;
        float l0 = acc[0];
#pragma unroll
        for (int e = 1; e < Ee; e++) if (acc[e] > l0) { l0 = acc[e]; e0 = e; }
        int e1 = -1;
        float l1 = -3.4e38f;
#pragma unroll
        for (int e = 0; e < Ee; e++) {
            if (e == e0) continue;
            if (acc[e] > l1) { l1 = acc[e]; e1 = e; }
        }
        float r = __expf(l1 - l0);           // <= 1
        float w0 = 1.0f / (1.0f + r);
        g_eidx[t * 2 + 0] = e0;
        g_eidx[t * 2 + 1] = e1;
        g_w[t * 2 + 0] = w0;
        g_w[t * 2 + 1] = 1.0f - w0;
    }
}

// ---------------- 2) Dispatch: pair-order cumsum per expert, capacity -------
__global__ void dispatch_kernel() {
    __shared__ int sc[256 * Ee];
    int tid = threadIdx.x;
    int base = tid * 64;               // 16384 pairs / 256 threads
    int lc[Ee];
#pragma unroll
    for (int e = 0; e < Ee; e++) lc[e] = 0;
    for (int p = base; p < base + 64; p++) lc[g_eidx[p]]++;
#pragma unroll
    for (int e = 0; e < Ee; e++) sc[tid * Ee + e] = lc[e];
    __syncthreads();
    if (tid < Ee) {
        int run = 0;
        for (int i = 0; i < 256; i++) {
            int v = sc[i * Ee + tid];
            sc[i * Ee + tid] = run;
            run += v;
        }
        g_cnt[tid] = run < CAPc ? run : CAPc;
    }
    __syncthreads();
    int off[Ee];
#pragma unroll
    for (int e = 0; e < Ee; e++) off[e] = sc[tid * Ee + e];
    for (int p = base; p < base + 64; p++) {
        int e = g_eidx[p];
        int pos = off[e]++;
        if (pos < CAPc) {
            int d = e * CAPc + pos;
            g_slot_token[d] = p >> 1;      // token id
            g_dest[p] = d;
        } else {
            g_dest[p] = -1;
        }
    }
}

// ---------------- 3) GEMM1: h = gelu(gather(x) @ W1[e] + b1[e]) -------------
__global__ void __launch_bounds__(256, 2)
gemm1_kernel(const float* __restrict__ x,
             const float* __restrict__ W1,
             const float* __restrict__ b1) {
    int e = blockIdx.z;
    int cnt = g_cnt[e];
    int m0 = blockIdx.y * BM;
    if (m0 >= cnt) return;
    int n0 = blockIdx.x * BN;

    __shared__ float As[BKK][BM];
    __shared__ float Bs[BKK][BN];

    int tid = threadIdx.x;
    int tx = tid & 15, ty = tid >> 4;

    // A-load assignment: each thread loads one float4 of one row
    int lrow = tid >> 1;
    int lq = (tid & 1) * 4;
    int gm = m0 + lrow;
    const float* arow = nullptr;
    if (gm < cnt) arow = x + (size_t)g_slot_token[e * CAPc + gm] * Dm;

    // B-load assignment
    int bk = tid >> 5;
    int bn4 = (tid & 31) * 4;
    const float* Wbase = W1 + (size_t)e * Dm * Hh;

    unsigned long long acc[8][4];
#pragma unroll
    for (int i = 0; i < 8; i++)
#pragma unroll
        for (int j = 0; j < 4; j++) acc[i][j] = 0ull;

    for (int k0 = 0; k0 < Dm; k0 += BKK) {
        float4 av = make_float4(0.f, 0.f, 0.f, 0.f);
        if (arow) av = *(const float4*)(arow + k0 + lq);
        As[lq + 0][lrow] = av.x;
        As[lq + 1][lrow] = av.y;
        As[lq + 2][lrow] = av.z;
        As[lq + 3][lrow] = av.w;
        *(float4*)&Bs[bk][bn4] =
            *(const float4*)(Wbase + (size_t)(k0 + bk) * Hh + n0 + bn4);
        __syncthreads();
#pragma unroll
        for (int kk = 0; kk < BKK; kk++) {
            float4 a0 = *(const float4*)&As[kk][ty * 8];
            float4 a1 = *(const float4*)&As[kk][ty * 8 + 4];
            float4 bq0 = *(const float4*)&Bs[kk][tx * 8];
            float4 bq1 = *(const float4*)&Bs[kk][tx * 8 + 4];
            unsigned long long bp[4];
            bp[0] = pk2(bq0.x, bq0.y); bp[1] = pk2(bq0.z, bq0.w);
            bp[2] = pk2(bq1.x, bq1.y); bp[3] = pk2(bq1.z, bq1.w);
            float aa[8] = {a0.x, a0.y, a0.z, a0.w, a1.x, a1.y, a1.z, a1.w};
#pragma unroll
            for (int i = 0; i < 8; i++) {
                unsigned long long ap = pk2(aa[i], aa[i]);
#pragma unroll
                for (int j = 0; j < 4; j++) FMA2(acc[i][j], ap, bp[j]);
            }
        }
        __syncthreads();
    }

    // epilogue: bias + gelu
#pragma unroll
    for (int i = 0; i < 8; i++) {
        int row = m0 + ty * 8 + i;
        float* hr = g_h + ((size_t)(e * CAPc + row)) * Hh;
#pragma unroll
        for (int j = 0; j < 4; j++) {
            float v0, v1;
            upk2(acc[i][j], v0, v1);
            int c = n0 + tx * 8 + j * 2;
            hr[c + 0] = gelu_tanh(v0 + b1[e * Hh + c + 0]);
            hr[c + 1] = gelu_tanh(v1 + b1[e * Hh + c + 1]);
        }
    }
}

// ---------------- 4) GEMM2: out = h @ W2[e] + b2[e] -------------------------
__global__ void __launch_bounds__(256, 2)
gemm2_kernel(const float* __restrict__ W2,
             const float* __restrict__ b2) {
    int e = blockIdx.z;
    int cnt = g_cnt[e];
    int m0 = blockIdx.y * BM;
    if (m0 >= cnt) return;
    int n0 = blockIdx.x * BN;

    __shared__ float As[BKK][BM];
    __shared__ float Bs[BKK][BN];

    int tid = threadIdx.x;
    int tx = tid & 15, ty = tid >> 4;

    int lrow = tid >> 1;
    int lq = (tid & 1) * 4;
    const float* arow = g_h + (size_t)(e * CAPc + m0 + lrow) * Hh;

    int bk = tid >> 5;
    int bn4 = (tid & 31) * 4;
    const float* Wbase = W2 + (size_t)e * Hh * Dm;

    unsigned long long acc[8][4];
#pragma unroll
    for (int i = 0; i < 8; i++)
#pragma unroll
        for (int j = 0; j < 4; j++) acc[i][j] = 0ull;

    for (int k0 = 0; k0 < Hh; k0 += BKK) {
        float4 av = *(const float4*)(arow + k0 + lq);
        As[lq + 0][lrow] = av.x;
        As[lq + 1][lrow] = av.y;
        As[lq + 2][lrow] = av.z;
        As[lq + 3][lrow] = av.w;
        *(float4*)&Bs[bk][bn4] =
            *(const float4*)(Wbase + (size_t)(k0 + bk) * Dm + n0 + bn4);
        __syncthreads();
#pragma unroll
        for (int kk = 0; kk < BKK; kk++) {
            float4 a0 = *(const float4*)&As[kk][ty * 8];
            float4 a1 = *(const float4*)&As[kk][ty * 8 + 4];
            float4 bq0 = *(const float4*)&Bs[kk][tx * 8];
            float4 bq1 = *(const float4*)&Bs[kk][tx * 8 + 4];
            unsigned long long bp[4];
            bp[0] = pk2(bq0.x, bq0.y); bp[1] = pk2(bq0.z, bq0.w);
            bp[2] = pk2(bq1.x, bq1.y); bp[3] = pk2(bq1.z, bq1.w);
            float aa[8] = {a0.x, a0.y, a0.z, a0.w, a1.x, a1.y, a1.z, a1.w};
#pragma unroll
            for (int i = 0; i < 8; i++) {
                unsigned long long ap = pk2(aa[i], aa[i]);
#pragma unroll
                for (int j = 0; j < 4; j++) FMA2(acc[i][j], ap, bp[j]);
            }
        }
        __syncthreads();
    }

#pragma unroll
    for (int i = 0; i < 8; i++) {
        int row = m0 + ty * 8 + i;
        float* orow = g_o + ((size_t)(e * CAPc + row)) * Dm;
#pragma unroll
        for (int j = 0; j < 4; j++) {
            float v0, v1;
            upk2(acc[i][j], v0, v1);
            int c = n0 + tx * 8 + j * 2;
            orow[c + 0] = v0 + b2[e * Dm + c + 0];
            orow[c + 1] = v1 + b2[e * Dm + c + 1];
        }
    }
}

// ---------------- 5) Combine: y[t] = sum_k w * out[dest] --------------------
__global__ void combine_kernel(float* __restrict__ y) {
    int t = blockIdx.x;
    int c4 = threadIdx.x * 4;
    float4 acc = make_float4(0.f, 0.f, 0.f, 0.f);
#pragma unroll
    for (int k = 0; k < Kk; k++) {
        int dst = g_dest[t * 2 + k];
        if (dst >= 0) {
            float w = g_w[t * 2 + k];
            float4 o = *(const float4*)(g_o + (size_t)dst * Dm + c4);
            acc.x += w * o.x;
            acc.y += w * o.y;
            acc.z += w * o.z;
            acc.w += w * o.w;
        }
    }
    *(float4*)(y + (size_t)t * Dm + c4) = acc;
}

// ---------------- launch ----------------------------------------------------
extern "C" void kernel_launch(void* const* d_in, const int* in_sizes, int n_in,
                              void* d_out, int out_size) {
    const float* x  = (const float*)d_in[0];
    const float* Wr = (const float*)d_in[1];
    const float* W1 = (const float*)d_in[2];
    const float* b1 = (const float*)d_in[3];
    const float* W2 = (const float*)d_in[4];
    const float* b2 = (const float*)d_in[5];
    float* y = (float*)d_out;

    router_kernel<<<Tt / 8, 256>>>(x, Wr);
    dispatch_kernel<<<1, 256>>>();
    gemm1_kernel<<<dim3(Hh / BN, CAPc / BM, Ee), 256>>>(x, W1, b1);
    gemm2_kernel<<<dim3(Dm / BN, CAPc / BM, Ee), 256>>>(W2, b2);
    combine_kernel<<<Tt, 256>>>(y);
}

// round 17
// speedup vs baseline: 3.0703x; 3.0670x over previous
#include <cuda_runtime.h>
#include <cuda_bf16.h>
#include <math.h>

typedef unsigned int u32;
typedef unsigned long long u64;
typedef unsigned short u16;

// Problem constants
#define Dm   1024
#define Hh   4096
#define Ee   8
#define Kk   2
#define Tt   8192
#define CAPc 2560

// ---------------- device scratch (no cudaMalloc allowed) --------------------
__device__ int   g_eidx[Tt * Kk];
__device__ float g_w[Tt * Kk];
__device__ int   g_dest[Tt * Kk];
__device__ int   g_slot_token[Ee * CAPc];
__device__ int   g_cnt[Ee];

__device__ __nv_bfloat16 g_xh[(size_t)Tt * Dm];
__device__ __nv_bfloat16 g_xl[(size_t)Tt * Dm];
__device__ __nv_bfloat16 g_w1h[(size_t)Ee * Hh * Dm];   // W1^T: [E][H][D]
__device__ __nv_bfloat16 g_w1l[(size_t)Ee * Hh * Dm];
__device__ __nv_bfloat16 g_w2h[(size_t)Ee * Dm * Hh];   // W2^T: [E][D][H]
__device__ __nv_bfloat16 g_w2l[(size_t)Ee * Dm * Hh];
__device__ __nv_bfloat16 g_hh[(size_t)Ee * CAPc * Hh];  // hidden acts hi
__device__ __nv_bfloat16 g_hl[(size_t)Ee * CAPc * Hh];  // hidden acts lo
__device__ float g_o[(size_t)Ee * CAPc * Dm];

// ---------------- helpers ---------------------------------------------------
__device__ __forceinline__ float gelu_tanh(float v) {
    float u = 0.7978845608028654f * (v + 0.044715f * v * v * v);
    return 0.5f * v * (1.0f + tanhf(u));
}
__device__ __forceinline__ u32 smem_u32(const void* p) {
    u32 a;
    asm("{ .reg .u64 t; cvta.to.shared.u64 t, %1; cvt.u32.u64 %0, t; }" : "=r"(a) : "l"(p));
    return a;
}
__device__ __forceinline__ u32 pack_bf2(__nv_bfloat16 a, __nv_bfloat16 b) {
    u16 ua = *reinterpret_cast<u16*>(&a);
    u16 ub = *reinterpret_cast<u16*>(&b);
    return (u32)ua | ((u32)ub << 16);
}
__device__ __forceinline__ void cp16(u32 s, const void* g, bool valid) {
    asm volatile("cp.async.cg.shared.global [%0], [%1], 16, %2;"
                 :: "r"(s), "l"(g), "r"(valid ? 16 : 0));
}
__device__ __forceinline__ void cp_commit() {
    asm volatile("cp.async.commit_group;" ::: "memory");
}
template <int N>
__device__ __forceinline__ void cp_wait() {
    asm volatile("cp.async.wait_group %0;" :: "n"(N) : "memory");
}
__device__ __forceinline__ void ldsm_x4(u32* r, u32 addr) {
    asm volatile("ldmatrix.sync.aligned.m8n8.x4.shared.b16 {%0,%1,%2,%3}, [%4];"
                 : "=r"(r[0]), "=r"(r[1]), "=r"(r[2]), "=r"(r[3]) : "r"(addr));
}
__device__ __forceinline__ void mma_bf16(float* d, const u32* a, const u32* b) {
    asm volatile(
        "mma.sync.aligned.m16n8k16.row.col.f32.bf16.bf16.f32 "
        "{%0,%1,%2,%3}, {%4,%5,%6,%7}, {%8,%9}, {%0,%1,%2,%3};"
        : "+f"(d[0]), "+f"(d[1]), "+f"(d[2]), "+f"(d[3])
        : "r"(a[0]), "r"(a[1]), "r"(a[2]), "r"(a[3]), "r"(b[0]), "r"(b[1]));
}

// ---------------- converts ---------------------------------------------------
__global__ void convert_x_kernel(const float* __restrict__ x) {
    size_t i = ((size_t)blockIdx.x * 256 + threadIdx.x) * 4;
    float4 v = *(const float4*)(x + i);
    __nv_bfloat16 h0 = __float2bfloat16(v.x), h1 = __float2bfloat16(v.y);
    __nv_bfloat16 h2 = __float2bfloat16(v.z), h3 = __float2bfloat16(v.w);
    float l0 = v.x - __bfloat162float(h0), l1 = v.y - __bfloat162float(h1);
    float l2 = v.z - __bfloat162float(h2), l3 = v.w - __bfloat162float(h3);
    *(uint2*)((char*)g_xh + i * 2) = make_uint2(pack_bf2(h0, h1), pack_bf2(h2, h3));
    *(uint2*)((char*)g_xl + i * 2) =
        make_uint2(pack_bf2(__float2bfloat16(l0), __float2bfloat16(l1)),
                   pack_bf2(__float2bfloat16(l2), __float2bfloat16(l3)));
}

// MODE 0: W1 [E][D][H] -> [E][H][D]; MODE 1: W2 [E][H][D] -> [E][D][H]
template <int MODE>
__global__ void transpose_split_kernel(const float* __restrict__ W) {
    constexpr int R = (MODE == 0) ? Dm : Hh;
    constexpr int C = (MODE == 0) ? Hh : Dm;
    __nv_bfloat16* oh = (MODE == 0) ? g_w1h : g_w2h;
    __nv_bfloat16* ol = (MODE == 0) ? g_w1l : g_w2l;
    __shared__ float tile[32][33];
    int e = blockIdx.z;
    int c0 = blockIdx.x * 32, r0 = blockIdx.y * 32;
    int tx = threadIdx.x, ty = threadIdx.y;
    const float* src = W + ((size_t)e * R + r0) * C + c0;
#pragma unroll
    for (int k = 0; k < 32; k += 8)
        tile[ty + k][tx] = src[(size_t)(ty + k) * C + tx];
    __syncthreads();
    size_t obase = ((size_t)e * C + c0) * R + r0;
#pragma unroll
    for (int k = 0; k < 32; k += 8) {
        float v = tile[tx][ty + k];
        __nv_bfloat16 h = __float2bfloat16(v);
        float lo = v - __bfloat162float(h);
        size_t oi = obase + (size_t)(ty + k) * R + tx;
        oh[oi] = h;
        ol[oi] = __float2bfloat16(lo);
    }
}

// ---------------- 1) Router --------------------------------------------------
__global__ void router_kernel(const float* __restrict__ x,
                              const float* __restrict__ Wr) {
    __shared__ float sWrT[Ee * Dm];
    for (int i = threadIdx.x; i < Dm * Ee; i += 256) {
        int d = i / Ee, e = i % Ee;
        sWrT[e * Dm + d] = Wr[i];
    }
    __syncthreads();
    int warp = threadIdx.x >> 5, lane = threadIdx.x & 31;
    int t = blockIdx.x * 8 + warp;
    const float* xr = x + (size_t)t * Dm;
    float acc[Ee];
#pragma unroll
    for (int e = 0; e < Ee; e++) acc[e] = 0.f;
    for (int d = lane * 4; d < Dm; d += 128) {
        float4 xv = *(const float4*)(xr + d);
#pragma unroll
        for (int e = 0; e < Ee; e++) {
            float4 wv = *(const float4*)(&sWrT[e * Dm + d]);
            acc[e] += xv.x * wv.x + xv.y * wv.y + xv.z * wv.z + xv.w * wv.w;
        }
    }
#pragma unroll
    for (int e = 0; e < Ee; e++) {
#pragma unroll
        for (int off = 16; off > 0; off >>= 1)
            acc[e] += __shfl_xor_sync(0xffffffffu, acc[e], off);
    }
    if (lane == 0) {
        int e0 = 0;
        float l0 = acc[0];
#pragma unroll
        for (int e = 1; e < Ee; e++) if (acc[e] > l0) { l0 = acc[e]; e0 = e; }
        int e1 = -1;
        float l1 = -3.4e38f;
#pragma unroll
        for (int e = 0; e < Ee; e++) {
            if (e == e0) continue;
            if (acc[e] > l1) { l1 = acc[e]; e1 = e; }
        }
        float r = __expf(l1 - l0);
        float w0 = 1.0f / (1.0f + r);
        g_eidx[t * 2 + 0] = e0;
        g_eidx[t * 2 + 1] = e1;
        g_w[t * 2 + 0] = w0;
        g_w[t * 2 + 1] = 1.0f - w0;
    }
}

// ---------------- 2) Dispatch ------------------------------------------------
__global__ void dispatch_kernel() {
    __shared__ int sc[256 * Ee];
    int tid = threadIdx.x;
    int base = tid * 64;
    int lc[Ee];
#pragma unroll
    for (int e = 0; e < Ee; e++) lc[e] = 0;
    for (int p = base; p < base + 64; p++) lc[g_eidx[p]]++;
#pragma unroll
    for (int e = 0; e < Ee; e++) sc[tid * Ee + e] = lc[e];
    __syncthreads();
    if (tid < Ee) {
        int run = 0;
        for (int i = 0; i < 256; i++) {
            int v = sc[i * Ee + tid];
            sc[i * Ee + tid] = run;
            run += v;
        }
        g_cnt[tid] = run < CAPc ? run : CAPc;
    }
    __syncthreads();
    int off[Ee];
#pragma unroll
    for (int e = 0; e < Ee; e++) off[e] = sc[tid * Ee + e];
    for (int p = base; p < base + 64; p++) {
        int e = g_eidx[p];
        int pos = off[e]++;
        if (pos < CAPc) {
            int d = e * CAPc + pos;
            g_slot_token[d] = p >> 1;
            g_dest[p] = d;
        } else {
            g_dest[p] = -1;
        }
    }
}

// ---------------- 3) Tensor-core grouped GEMM via mma.sync bf16 split -------
// CTA tile 128x128, Kc=64, 8 warps (2x4), warp tile 64x32.
// SMEM stage: Ah(16K) Al(16K) Bh(16K) Bl(16K) = 64KB, double-buffered = 128KB.
// 128B rows, XOR swizzle: phys_unit = c ^ (r&7)  (16B units).
#define KC 64
#define STAGE_BYTES 65536
#define SMEM_TOTAL  (2 * STAGE_BYTES)

template <int MODE>
__global__ void __launch_bounds__(256, 1)
mma_gemm_kernel(const float* __restrict__ bias) {
    constexpr int Kdim = (MODE == 0) ? Dm : Hh;
    constexpr int NOut = (MODE == 0) ? Hh : Dm;
    constexpr int NC = Kdim / KC;

    int e = blockIdx.z;
    int cnt = g_cnt[e];
    int m0 = blockIdx.y * 128;
    if (m0 >= cnt) return;
    int n0 = blockIdx.x * 128;

    extern __shared__ char smem[];
    u32 sb = smem_u32(smem);
    int tid = threadIdx.x;
    int wid = tid >> 5, lane = tid & 31;
    int wm = wid >> 2, wn = wid & 3;

    // ---- per-thread cp.async slots: idx = slot*256+tid; r=idx>>3 (row), c=idx&7 (16B unit)
    u32 swo[4];
    const char* aptr[4];
    const char* bptr[4];
    bool aval[4];
#pragma unroll
    for (int i = 0; i < 4; i++) {
        int idx = i * 256 + tid;
        int r = idx >> 3, c = idx & 7;
        swo[i] = (u32)(r * 128 + ((c ^ (r & 7)) << 4));
        if (MODE == 0) {
            int gm = m0 + r;
            aval[i] = gm < cnt;
            int tok = aval[i] ? g_slot_token[e * CAPc + gm] : 0;
            aptr[i] = (const char*)(g_xh + (size_t)tok * Dm) + c * 16;
            bptr[i] = (const char*)(g_w1h + ((size_t)e * Hh + n0 + r) * Dm) + c * 16;
        } else {
            aval[i] = true;
            aptr[i] = (const char*)(g_hh + (size_t)(e * CAPc + m0 + r) * Hh) + c * 16;
            bptr[i] = (const char*)(g_w2h + ((size_t)e * Dm + n0 + r) * Hh) + c * 16;
        }
    }
    const size_t aloff = (MODE == 0)
        ? (size_t)((const char*)g_xl - (const char*)g_xh)
        : (size_t)((const char*)g_hl - (const char*)g_hh);
    const size_t bloff = (MODE == 0)
        ? (size_t)((const char*)g_w1l - (const char*)g_w1h)
        : (size_t)((const char*)g_w2l - (const char*)g_w2h);

    // ---- ldmatrix lane address components
    // A x4 frag (16m x 16k): mats {r0-7,k0 | r8-15,k0 | r0-7,k8 | r8-15,k8}
    int a_rin = ((lane >> 3) & 1) * 8 + (lane & 7);
    int a_uin = lane >> 4;                     // +unit within k-step
    // B x4 frag (16n x 16k): mats {n0-7,k0 | n0-7,k8 | n8-15,k0 | n8-15,k8}
    int b_rin = ((lane >> 4) & 1) * 8 + (lane & 7);
    int b_uin = (lane >> 3) & 1;

    u32 a_rb[4], a_rm[4];
#pragma unroll
    for (int mp = 0; mp < 4; mp++) {
        int row = wm * 64 + mp * 16 + a_rin;
        a_rb[mp] = row * 128;
        a_rm[mp] = row & 7;
    }
    u32 b_rb[2], b_rm[2];
#pragma unroll
    for (int np2 = 0; np2 < 2; np2++) {
        int row = wn * 32 + np2 * 16 + b_rin;
        b_rb[np2] = row * 128;
        b_rm[np2] = row & 7;
    }

    float acc[4][4][4];
#pragma unroll
    for (int i = 0; i < 4; i++)
#pragma unroll
        for (int j = 0; j < 4; j++)
#pragma unroll
            for (int q = 0; q < 4; q++) acc[i][j][q] = 0.f;

    // ---- issue lambda-ish macro
#define ISSUE(ST, CH)                                                          \
    do {                                                                       \
        u32 s0 = sb + (ST) * STAGE_BYTES;                                      \
        size_t ko = (size_t)(CH) * (KC * 2);                                   \
        _Pragma("unroll")                                                      \
        for (int i = 0; i < 4; i++) {                                          \
            cp16(s0 + swo[i],         aptr[i] + ko, aval[i]);                  \
            cp16(s0 + 16384 + swo[i], aptr[i] + aloff + ko, aval[i]);          \
            cp16(s0 + 32768 + swo[i], bptr[i] + ko, true);                     \
            cp16(s0 + 49152 + swo[i], bptr[i] + bloff + ko, true);             \
        }                                                                      \
        cp_commit();                                                           \
    } while (0)

    ISSUE(0, 0);

    for (int ch = 0; ch < NC; ch++) {
        if (ch + 1 < NC) {
            ISSUE((ch + 1) & 1, ch + 1);
            cp_wait<1>();
        } else {
            cp_wait<0>();
        }
        __syncthreads();

        u32 st = sb + (u32)(ch & 1) * STAGE_BYTES;
#pragma unroll
        for (int kk = 0; kk < KC / 16; kk++) {
            u32 ah[4][4], al[4][4];
#pragma unroll
            for (int mp = 0; mp < 4; mp++) {
                u32 u = 2 * kk + a_uin;
                u32 ad = st + a_rb[mp] + ((u ^ a_rm[mp]) << 4);
                ldsm_x4(ah[mp], ad);
                ldsm_x4(al[mp], ad + 16384);
            }
            u32 bh[2][4], bl[2][4];
#pragma unroll
            for (int np2 = 0; np2 < 2; np2++) {
                u32 u = 2 * kk + b_uin;
                u32 bd = st + 32768 + b_rb[np2] + ((u ^ b_rm[np2]) << 4);
                ldsm_x4(bh[np2], bd);
                ldsm_x4(bl[np2], bd + 16384);
            }
#pragma unroll
            for (int mp = 0; mp < 4; mp++) {
#pragma unroll
                for (int np = 0; np < 4; np++) {
                    const u32* ph = &bh[np >> 1][(np & 1) * 2];
                    const u32* pl = &bl[np >> 1][(np & 1) * 2];
                    mma_bf16(acc[mp][np], ah[mp], ph);
                    mma_bf16(acc[mp][np], ah[mp], pl);
                    mma_bf16(acc[mp][np], al[mp], ph);
                }
            }
        }
        __syncthreads();
    }
#undef ISSUE

    // ---- epilogue ----
    const float* be = bias + (size_t)e * NOut;
#pragma unroll
    for (int mp = 0; mp < 4; mp++) {
        int lr = wm * 64 + mp * 16 + (lane >> 2);
        size_t row0 = (size_t)(e * CAPc + m0 + lr);
#pragma unroll
        for (int np = 0; np < 4; np++) {
            int col = n0 + wn * 32 + np * 8 + (lane & 3) * 2;
            float2 bv = __ldg((const float2*)(be + col));
            float* a4 = acc[mp][np];
            float v0 = a4[0] + bv.x, v1 = a4[1] + bv.y;
            float v2 = a4[2] + bv.x, v3 = a4[3] + bv.y;
            if (MODE == 0) {
                v0 = gelu_tanh(v0); v1 = gelu_tanh(v1);
                v2 = gelu_tanh(v2); v3 = gelu_tanh(v3);
                __nv_bfloat16 h0 = __float2bfloat16(v0), h1 = __float2bfloat16(v1);
                __nv_bfloat16 h2 = __float2bfloat16(v2), h3 = __float2bfloat16(v3);
                u32 lo01 = pack_bf2(__float2bfloat16(v0 - __bfloat162float(h0)),
                                    __float2bfloat16(v1 - __bfloat162float(h1)));
                u32 lo23 = pack_bf2(__float2bfloat16(v2 - __bfloat162float(h2)),
                                    __float2bfloat16(v3 - __bfloat162float(h3)));
                *(u32*)((char*)g_hh + (row0 * Hh + col) * 2) = pack_bf2(h0, h1);
                *(u32*)((char*)g_hl + (row0 * Hh + col) * 2) = lo01;
                *(u32*)((char*)g_hh + ((row0 + 8) * Hh + col) * 2) = pack_bf2(h2, h3);
                *(u32*)((char*)g_hl + ((row0 + 8) * Hh + col) * 2) = lo23;
            } else {
                *(float2*)(g_o + row0 * Dm + col) = make_float2(v0, v1);
                *(float2*)(g_o + (row0 + 8) * Dm + col) = make_float2(v2, v3);
            }
        }
    }
}

// ---------------- 5) Combine -------------------------------------------------
__global__ void combine_kernel(float* __restrict__ y) {
    int t = blockIdx.x;
    int c4 = threadIdx.x * 4;
    float4 acc = make_float4(0.f, 0.f, 0.f, 0.f);
#pragma unroll
    for (int k = 0; k < Kk; k++) {
        int dst = g_dest[t * 2 + k];
        if (dst >= 0) {
            float w = g_w[t * 2 + k];
            float4 o = *(const float4*)(g_o + (size_t)dst * Dm + c4);
            acc.x += w * o.x;
            acc.y += w * o.y;
            acc.z += w * o.z;
            acc.w += w * o.w;
        }
    }
    *(float4*)(y + (size_t)t * Dm + c4) = acc;
}

// ---------------- launch -----------------------------------------------------
extern "C" void kernel_launch(void* const* d_in, const int* in_sizes, int n_in,
                              void* d_out, int out_size) {
    const float* x  = (const float*)d_in[0];
    const float* Wr = (const float*)d_in[1];
    const float* W1 = (const float*)d_in[2];
    const float* b1 = (const float*)d_in[3];
    const float* W2 = (const float*)d_in[4];
    const float* b2 = (const float*)d_in[5];
    float* y = (float*)d_out;

    static bool attr_done = false;
    if (!attr_done) {
        cudaFuncSetAttribute(mma_gemm_kernel<0>,
                             cudaFuncAttributeMaxDynamicSharedMemorySize, SMEM_TOTAL);
        cudaFuncSetAttribute(mma_gemm_kernel<1>,
                             cudaFuncAttributeMaxDynamicSharedMemorySize, SMEM_TOTAL);
        attr_done = true;
    }

    convert_x_kernel<<<(Tt * Dm) / 1024, 256>>>(x);
    transpose_split_kernel<0><<<dim3(Hh / 32, Dm / 32, Ee), dim3(32, 8)>>>(W1);
    transpose_split_kernel<1><<<dim3(Dm / 32, Hh / 32, Ee), dim3(32, 8)>>>(W2);
    router_kernel<<<Tt / 8, 256>>>(x, Wr);
    dispatch_kernel<<<1, 256>>>();
    mma_gemm_kernel<0><<<dim3(Hh / 128, CAPc / 128, Ee), 256, SMEM_TOTAL>>>(b1);
    mma_gemm_kernel<1><<<dim3(Dm / 128, CAPc / 128, Ee), 256, SMEM_TOTAL>>>(b2);
    combine_kernel<<<Tt, 256>>>(y);
}